// round 16
// baseline (speedup 1.0000x reference)
#include <cuda_runtime.h>
#include <cuda_bf16.h>
#include <math.h>
#include <stdint.h>

// ContrastLoss: feat [4,64,512,512] f32, gt [4,19,512,512] i32 -> scalar f32

#define NPIX   (4 * 262144)
#define HW     262144
#define KCLS   19
#define CCH    64
#define TAUF   0.07f
#define LOG2E  1.4426950408889634f
#define CH64   16384               // NPIX / 64 chunks

// -------- device scratch --------
__device__ float    g_k0[KCLS * CCH];
__device__ unsigned g_maskbuf[NPIX];
__device__ float    g_ssum[NPIX];          // per-pixel ||f||^2 (from k_proto)
__device__ int      g_cnt[1024];
__device__ double   g_loss;

// ======== f32x2 helpers ========
__device__ __forceinline__ unsigned long long pack2(float a, float b) {
    unsigned long long r;
    asm("mov.b64 %0, {%1, %2};" : "=l"(r) : "f"(a), "f"(b));
    return r;
}
__device__ __forceinline__ void unpack2(unsigned long long v, float& a, float& b) {
    asm("mov.b64 {%0, %1}, %2;" : "=f"(a), "=f"(b) : "l"(v));
}
__device__ __forceinline__ void ffma2(unsigned long long& d, unsigned long long a,
                                      unsigned long long b) {
    asm("fma.rn.f32x2 %0, %1, %2, %0;" : "+l"(d) : "l"(a), "l"(b));
}

// ======== bf16 hi/lo pack: low16 = bf16(f), high16 = bf16(f - float(bf16(f))) ====
__device__ __forceinline__ uint32_t hilo(float f) {
    uint32_t h;
    asm("cvt.rn.bf16x2.f32 %0, %1, %2;" : "=r"(h) : "f"(0.f), "f"(f));
    const float hf = __uint_as_float(h << 16);
    const float lo = f - hf;
    uint32_t r;
    asm("cvt.rn.bf16x2.f32 %0, %1, %2;" : "=r"(r) : "f"(lo), "f"(f));
    return r;
}

// ======== warp MMA m16n8k16 bf16 ========
__device__ __forceinline__ void mma16816(float* d, uint32_t a0, uint32_t a1,
                                         uint32_t a2, uint32_t a3,
                                         uint32_t b0, uint32_t b1) {
    asm volatile(
        "mma.sync.aligned.m16n8k16.row.col.f32.bf16.bf16.f32 "
        "{%0,%1,%2,%3}, {%4,%5,%6,%7}, {%8,%9}, {%0,%1,%2,%3};"
        : "+f"(d[0]), "+f"(d[1]), "+f"(d[2]), "+f"(d[3])
        : "r"(a0), "r"(a1), "r"(a2), "r"(a3), "r"(b0), "r"(b1));
}

// -------- launch 1: zero accumulators --------
__global__ void k_zero() {
    int t = blockIdx.x * 256 + threadIdx.x;
    if (t < KCLS * CCH) g_k0[t] = 0.f;
    if (t == 0) g_loss = 0.0;
}

// -------- launch 0: build 19-bit pixel masks + per-block pos counts --------
__global__ __launch_bounds__(256) void k_mask(const int* __restrict__ gt) {
    const int p4 = (blockIdx.x * 256 + threadIdx.x) * 4;   // 1024 blocks exactly
    const int b  = p4 >> 18;
    const int hw = p4 & (HW - 1);
    unsigned m0 = 0, m1 = 0, m2 = 0, m3 = 0;
#pragma unroll
    for (int k = 0; k < KCLS; k++) {
        const int4 g = *reinterpret_cast<const int4*>(
            gt + (size_t)(b * KCLS + k) * HW + hw);
        m0 |= (unsigned)(g.x == 1) << k;
        m1 |= (unsigned)(g.y == 1) << k;
        m2 |= (unsigned)(g.z == 1) << k;
        m3 |= (unsigned)(g.w == 1) << k;
    }
    *reinterpret_cast<uint4*>(&g_maskbuf[p4]) = make_uint4(m0, m1, m2, m3);
    int cnt = __popc(m0) + __popc(m1) + __popc(m2) + __popc(m3);
#pragma unroll
    for (int o = 16; o; o >>= 1) cnt += __shfl_xor_sync(0xffffffffu, cnt, o);
    __shared__ int sc[8];
    if ((threadIdx.x & 31) == 0) sc[threadIdx.x >> 5] = cnt;
    __syncthreads();
    if (threadIdx.x == 0) {
        int s = 0;
#pragma unroll
        for (int w = 0; w < 8; w++) s += sc[w];
        g_cnt[blockIdx.x] = s;
    }
}

// -------- launch 2: smem-staged HMMA prototype GEMM + ||f||^2 precompute ------
__global__ __launch_bounds__(256, 4) void k_proto_mma(const float* __restrict__ feat) {
    __shared__ uint32_t sA[64 * 80];
    __shared__ uint32_t sM[64];
    __shared__ float    sk0[KCLS * CCH];
    __shared__ float    ssp[64];

    const int tid  = threadIdx.x;
    const int w    = tid >> 5;
    const int lane = tid & 31;
    const int g    = lane >> 2;
    const int t    = lane & 3;
    const int chb  = (w & 3) * 16;
    const int hb   = (w >> 2) * 32;
    const int sc_hi = lane >> 4;
    const int sc_px = (lane & 15) * 4;

    for (int i = tid; i < KCLS * CCH; i += 256) sk0[i] = 0.f;
    if (tid < 64) ssp[tid] = 0.f;

    float d0[4] = {0.f, 0.f, 0.f, 0.f};
    float d1[4] = {0.f, 0.f, 0.f, 0.f};
    float d2[4] = {0.f, 0.f, 0.f, 0.f};

    for (int chunk = blockIdx.x; chunk < CH64; chunk += gridDim.x) {
        const int P  = chunk * 64;
        const int b  = P >> 18;
        const int hw = P & (HW - 1);
        __syncthreads();   // bar1: prev MMA reads + prev ssp write-out/reset done

        float ps0 = 0.f, ps1 = 0.f, ps2 = 0.f, ps3 = 0.f;
#pragma unroll
        for (int i = 0; i < 4; i++) {
            const int ch = w * 8 + 2 * i + sc_hi;
            const float4 f = *reinterpret_cast<const float4*>(
                feat + (size_t)(b * CCH + ch) * HW + hw + sc_px);
            ps0 = fmaf(f.x, f.x, ps0);
            ps1 = fmaf(f.y, f.y, ps1);
            ps2 = fmaf(f.z, f.z, ps2);
            ps3 = fmaf(f.w, f.w, ps3);
            const uint32_t h0 = hilo(f.x);
            const uint32_t h1 = hilo(f.y);
            const uint32_t h2 = hilo(f.z);
            const uint32_t h3 = hilo(f.w);
            const int word = ch * 80 + (sc_px ^ ((ch & 3) << 3));
            *reinterpret_cast<uint4*>(&sA[word]) = make_uint4(h0, h1, h2, h3);
        }
        // combine channel-partners (lane^16 spans the other 4 channels of this px)
        ps0 += __shfl_xor_sync(0xffffffffu, ps0, 16);
        ps1 += __shfl_xor_sync(0xffffffffu, ps1, 16);
        ps2 += __shfl_xor_sync(0xffffffffu, ps2, 16);
        ps3 += __shfl_xor_sync(0xffffffffu, ps3, 16);
        if (sc_hi == 0) {
            atomicAdd(&ssp[sc_px + 0], ps0);
            atomicAdd(&ssp[sc_px + 1], ps1);
            atomicAdd(&ssp[sc_px + 2], ps2);
            atomicAdd(&ssp[sc_px + 3], ps3);
        }
        if (tid < 16)
            *reinterpret_cast<uint4*>(&sM[tid * 4]) =
                *reinterpret_cast<const uint4*>(&g_maskbuf[P + tid * 4]);
        __syncthreads();   // bar2: sA + ssp complete

        // write out ||f||^2 for this chunk, reset ssp for the next one
        if (tid < 64) {
            g_ssum[P + tid] = ssp[tid];
            ssp[tid] = 0.f;
        }

#pragma unroll
        for (int s = 0; s < 4; s++) {
            const int px = hb + 8 * s + 2 * t;
            const int sw = px ^ ((g & 3) << 3);
            const uint2 A0 = *reinterpret_cast<const uint2*>(&sA[(chb + g) * 80 + sw]);
            const uint2 A1 = *reinterpret_cast<const uint2*>(&sA[(chb + g + 8) * 80 + sw]);
            const uint2 M  = *reinterpret_cast<const uint2*>(&sM[px]);
            {
                const uint32_t b0 = ((M.x >> g) & 1u) * 0x3F803F80u;
                const uint32_t b1 = ((M.y >> g) & 1u) * 0x3F803F80u;
                mma16816(d0, A0.x, A1.x, A0.y, A1.y, b0, b1);
            }
            {
                const uint32_t b0 = ((M.x >> (8 + g)) & 1u) * 0x3F803F80u;
                const uint32_t b1 = ((M.y >> (8 + g)) & 1u) * 0x3F803F80u;
                mma16816(d1, A0.x, A1.x, A0.y, A1.y, b0, b1);
            }
            {
                const uint32_t b0 = ((M.x >> (16 + g)) & 1u) * 0x3F803F80u;
                const uint32_t b1 = ((M.y >> (16 + g)) & 1u) * 0x3F803F80u;
                mma16816(d2, A0.x, A1.x, A0.y, A1.y, b0, b1);
            }
        }
    }

    __syncthreads();
    {
        const int c0 = chb + g;
        const int c1 = chb + g + 8;
        const int k0c = 2 * t, k1c = 2 * t + 1;
        atomicAdd(&sk0[(k0c)     * CCH + c0], d0[0]);
        atomicAdd(&sk0[(k1c)     * CCH + c0], d0[1]);
        atomicAdd(&sk0[(k0c)     * CCH + c1], d0[2]);
        atomicAdd(&sk0[(k1c)     * CCH + c1], d0[3]);
        atomicAdd(&sk0[(8 + k0c) * CCH + c0], d1[0]);
        atomicAdd(&sk0[(8 + k1c) * CCH + c0], d1[1]);
        atomicAdd(&sk0[(8 + k0c) * CCH + c1], d1[2]);
        atomicAdd(&sk0[(8 + k1c) * CCH + c1], d1[3]);
        if (16 + k0c < KCLS) {
            atomicAdd(&sk0[(16 + k0c) * CCH + c0], d2[0]);
            atomicAdd(&sk0[(16 + k0c) * CCH + c1], d2[2]);
        }
        if (16 + k1c < KCLS) {
            atomicAdd(&sk0[(16 + k1c) * CCH + c0], d2[1]);
            atomicAdd(&sk0[(16 + k1c) * CCH + c1], d2[3]);
        }
    }
    __syncthreads();
    for (int i = tid; i < KCLS * CCH; i += 256) atomicAdd(&g_k0[i], sk0[i]);
}

// -------- per-pixel softmax/NLL (tau pre-folded into prototypes) --------
__device__ __forceinline__ float pix_loss(const float* __restrict__ l,
                                          float ssum, unsigned m) {
    const float sc = 1.f / fmaxf(sqrtf(ssum), 1e-12f);
    float v[KCLS];
    float mx = -1e30f;
#pragma unroll
    for (int k = 0; k < KCLS; k++) {
        v[k] = l[k] * sc;
        mx = fmaxf(mx, v[k]);
    }
    float se = 0.f, sl = 0.f;
#pragma unroll
    for (int k = 0; k < KCLS; k++) {
        se += exp2f((v[k] - mx) * LOG2E);
        if (m & (1u << k)) sl += v[k];
    }
    return (float)__popc(m) * (mx + logf(se)) - sl;
}

// -------- launch 3: fp32 logits + softmax NLL, 4 px/thread (PROFILED) --------
// R16: ||f||^2 read from g_ssum (ss FFMA2s removed), depth-1 software pipeline
// (prefetch next c4's 4 channel quads while computing current).
__global__ __launch_bounds__(256, 2) void k_loss(const float* __restrict__ feat) {
    __shared__ unsigned long long sknd[KCLS * CCH];   // (kn/tau, kn/tau) duplicated
    __shared__ float sinv[KCLS];
    if (threadIdx.x < KCLS) {
        float s = 0.f;
#pragma unroll
        for (int c = 0; c < CCH; c++) {
            const float v = g_k0[threadIdx.x * CCH + c];
            s = fmaf(v, v, s);
        }
        sinv[threadIdx.x] = 1.f / (fmaxf(sqrtf(s), 1e-12f) * TAUF);
    }
    __syncthreads();
    for (int t = threadIdx.x; t < KCLS * CCH; t += 256) {
        const float v = g_k0[t] * sinv[t >> 6];
        sknd[t] = pack2(v, v);
    }
    __syncthreads();

    const int p4 = (blockIdx.x * 256 + threadIdx.x) * 4;   // 1024 blocks exactly
    const uint4  m   = *reinterpret_cast<const uint4*>(&g_maskbuf[p4]);
    const float4 ssv = *reinterpret_cast<const float4*>(&g_ssum[p4]);
    const int   b  = p4 >> 18;
    const int   hw = p4 & (HW - 1);
    const float* fb = feat + (size_t)(b * CCH) * HW + hw;

    unsigned long long acca[KCLS], accb[KCLS];
#pragma unroll
    for (int k = 0; k < KCLS; k++) { acca[k] = 0ull; accb[k] = 0ull; }

    // depth-1 pipeline: preload c4=0; in iter, prefetch c4+1 (wrap), compute c4
    float4 f0 = *reinterpret_cast<const float4*>(fb + (size_t)0 * HW);
    float4 f1 = *reinterpret_cast<const float4*>(fb + (size_t)1 * HW);
    float4 f2 = *reinterpret_cast<const float4*>(fb + (size_t)2 * HW);
    float4 f3 = *reinterpret_cast<const float4*>(fb + (size_t)3 * HW);

#pragma unroll 1
    for (int c4 = 0; c4 < 16; c4++) {
        const int nc = (c4 + 1) & 15;      // wrap: last prefetch is harmless
        const float4 n0 = *reinterpret_cast<const float4*>(fb + (size_t)(4 * nc + 0) * HW);
        const float4 n1 = *reinterpret_cast<const float4*>(fb + (size_t)(4 * nc + 1) * HW);
        const float4 n2 = *reinterpret_cast<const float4*>(fb + (size_t)(4 * nc + 2) * HW);
        const float4 n3 = *reinterpret_cast<const float4*>(fb + (size_t)(4 * nc + 3) * HW);

        const unsigned long long A0 = pack2(f0.x, f0.y), B0 = pack2(f0.z, f0.w);
        const unsigned long long A1 = pack2(f1.x, f1.y), B1 = pack2(f1.z, f1.w);
        const unsigned long long A2 = pack2(f2.x, f2.y), B2 = pack2(f2.z, f2.w);
        const unsigned long long A3 = pack2(f3.x, f3.y), B3 = pack2(f3.z, f3.w);
#pragma unroll
        for (int k = 0; k < KCLS; k++) {
            const ulonglong2 k01 =
                *reinterpret_cast<const ulonglong2*>(&sknd[k * CCH + 4 * c4]);
            const ulonglong2 k23 =
                *reinterpret_cast<const ulonglong2*>(&sknd[k * CCH + 4 * c4 + 2]);
            ffma2(acca[k], A0, k01.x); ffma2(accb[k], B0, k01.x);
            ffma2(acca[k], A1, k01.y); ffma2(accb[k], B1, k01.y);
            ffma2(acca[k], A2, k23.x); ffma2(accb[k], B2, k23.x);
            ffma2(acca[k], A3, k23.y); ffma2(accb[k], B3, k23.y);
        }
        f0 = n0; f1 = n1; f2 = n2; f3 = n3;
    }

    float l0[KCLS], l1[KCLS], l2[KCLS], l3[KCLS];
#pragma unroll
    for (int k = 0; k < KCLS; k++) {
        unpack2(acca[k], l0[k], l1[k]);
        unpack2(accb[k], l2[k], l3[k]);
    }
    float lsum = pix_loss(l0, ssv.x, m.x) + pix_loss(l1, ssv.y, m.y)
               + pix_loss(l2, ssv.z, m.z) + pix_loss(l3, ssv.w, m.w);

    // block reduction -> double atomic
#pragma unroll
    for (int o = 16; o; o >>= 1) lsum += __shfl_xor_sync(0xffffffffu, lsum, o);
    __shared__ float wsum[8];
    if ((threadIdx.x & 31) == 0) wsum[threadIdx.x >> 5] = lsum;
    __syncthreads();
    if (threadIdx.x < 8) {
        float v = wsum[threadIdx.x];
#pragma unroll
        for (int o = 4; o; o >>= 1) v += __shfl_xor_sync(0x000000ffu, v, o);
        if (threadIdx.x == 0) atomicAdd(&g_loss, (double)v);
    }
}

// -------- launch 4: finalize --------
__global__ void k_fin(float* out) {
    int s = 0;
    for (int t = threadIdx.x; t < 1024; t += 256) s += g_cnt[t];
#pragma unroll
    for (int o = 16; o; o >>= 1) s += __shfl_xor_sync(0xffffffffu, s, o);
    __shared__ int ws[8];
    if ((threadIdx.x & 31) == 0) ws[threadIdx.x >> 5] = s;
    __syncthreads();
    if (threadIdx.x == 0) {
        int np = 0;
#pragma unroll
        for (int w = 0; w < 8; w++) np += ws[w];
        out[0] = (float)(g_loss / (double)(np > 0 ? np : 1));
    }
}

extern "C" void kernel_launch(void* const* d_in, const int* in_sizes, int n_in,
                              void* d_out, int out_size) {
    const float* feat = (const float*)d_in[0];
    const int*   gt   = (const int*)d_in[1];
    float*       out  = (float*)d_out;

    k_mask     <<<NPIX / (256 * 4), 256>>>(gt);
    k_zero     <<<5, 256>>>();
    k_proto_mma<<<592, 256>>>(feat);
    k_loss     <<<NPIX / (256 * 4), 256>>>(feat);
    k_fin      <<<1, 256>>>(out);
}